// round 3
// baseline (speedup 1.0000x reference)
#include <cuda_runtime.h>
#include <cuda_bf16.h>

// Output layout: [muTE (N floats)] ++ [M (N*N floats, row-major)]
// h = 0 (hunter), p = 1 (prey). N = 8192 for this problem.
//
// M is zero except rows/cols 0 and 1:
//   row 0: +v[j], row 1: -v[j], col 0: +v[i], col 1: -v[i]
//   2x2 corner handled specially. v[0]=v[1]=0.
//   v[j] = mu[j]*(var01 - 2*mu0*mu1) + mu1*var[0,j] + mu0*var[1,j]
//   (var[:,0] == var[0,:] bitwise, since var = 0.5*(a + a^T)).

#define TPB 256u
#define VPT 8u
#define ROW_SLOTS (TPB * VPT)        // 2048 float4 slots = 8192 floats = one row

__device__ __forceinline__ void corner2x2(const float* __restrict__ mu,
                                          const float* __restrict__ var,
                                          unsigned int N, unsigned int row,
                                          float* x, float* y) {
    float mu0   = __ldg(&mu[0]);
    float mu1   = __ldg(&mu[1]);
    float var01 = __ldg(&var[1]);
    float var00 = __ldg(&var[0]);
    float var11 = __ldg(&var[N + 1]);
    float hp = var01;
    float n3_pph = -2.f * mu1 * mu1 * mu0 + 2.f * mu1 * var01 + mu0 * var11;
    float n3_hhp = -2.f * mu0 * mu0 * mu1 + 2.f * mu0 * var01 + mu1 * var00;
    float n3_hpp = -2.f * mu0 * mu1 * mu1 + mu0 * var11 + 2.f * mu1 * var01;
    float chp = -n3_hhp + n3_hpp - hp;
    if (row == 0u) { *x = 2.f * n3_hhp + hp; *y = chp; }
    else           { *x = chp;               *y = -2.f * n3_pph + hp; }
}

// Specialized kernel: one block == one output row (N == 8192 exactly fills
// a block's TPB*VPT float4 slots). Block 0 = muTE, block 1+r = row r of M.
__global__ void __launch_bounds__(TPB)
eatrxn_row_kernel(const float* __restrict__ mu,
                  const float* __restrict__ var,
                  float* __restrict__ out,
                  unsigned int N) {
    unsigned int b = blockIdx.x;
    float4* __restrict__ out4 =
        reinterpret_cast<float4*>(out) + (size_t)b * ROW_SLOTS + threadIdx.x;

    const float4 z = make_float4(0.f, 0.f, 0.f, 0.f);

    if (b == 0u) {
        // muTE: zeros except first two floats
        float4 r0 = z;
        if (threadIdx.x == 0u) {
            float hp = __ldg(&var[1]);
            r0.x = hp; r0.y = -hp;
        }
        __stcs(&out4[0], r0);
        #pragma unroll
        for (unsigned int k = 1; k < VPT; ++k) __stcs(&out4[k * TPB], z);
        return;
    }

    unsigned int row = b - 1u;

    if (row < 2u) {
        // Dense rows 0/1: value = s * v[j..j+3] per slot
        float mu0   = __ldg(&mu[0]);
        float mu1   = __ldg(&mu[1]);
        float var01 = __ldg(&var[1]);
        float c = var01 - 2.f * mu0 * mu1;
        float s = (row == 0u) ? 1.f : -1.f;
        #pragma unroll
        for (unsigned int k = 0; k < VPT; ++k) {
            unsigned int j = (k * TPB + threadIdx.x) << 2;
            float4 r;
            float* rr = &r.x;
            #pragma unroll
            for (int q = 0; q < 4; ++q) {
                unsigned int jj = j + (unsigned int)q;
                float vj;
                if (jj < 2u) {
                    vj = 0.f;   // loop excludes j == prey and j == hunter
                } else {
                    vj = fmaf(__ldg(&mu[jj]), c,
                          fmaf(mu1, __ldg(&var[jj]),         // var[0, jj]
                               mu0 * __ldg(&var[N + jj])));  // var[1, jj]
                }
                rr[q] = s * vj;
            }
            if (k == 0u && threadIdx.x == 0u) {
                corner2x2(mu, var, N, row, &r.x, &r.y);
            }
            __stcs(&out4[k * TPB], r);
        }
        return;
    }

    // Bulk row (row >= 2): zeros everywhere except first float4 (cols 0/1)
    {
        float4 r0 = z;
        if (threadIdx.x == 0u) {
            float mu0   = __ldg(&mu[0]);
            float mu1   = __ldg(&mu[1]);
            float var01 = __ldg(&var[1]);
            float c = var01 - 2.f * mu0 * mu1;
            float vi = fmaf(__ldg(&mu[row]), c,
                        fmaf(mu1, __ldg(&var[row]),            // var[0, row]
                             mu0 * __ldg(&var[N + row])));     // var[1, row]
            r0.x = vi; r0.y = -vi;
        }
        __stcs(&out4[0], r0);
        #pragma unroll
        for (unsigned int k = 1; k < VPT; ++k) __stcs(&out4[k * TPB], z);
    }
}

// ---------------- Generic fallback (any N, any out_size) ----------------
__global__ void eatrxn_generic_kernel(const float* __restrict__ mu,
                                      const float* __restrict__ var,
                                      float* __restrict__ out,
                                      unsigned int total4,
                                      unsigned int N,
                                      unsigned int shift,
                                      unsigned int mask) {
    unsigned int base = blockIdx.x * (TPB * 4u) + threadIdx.x;
    float4* __restrict__ out4 = reinterpret_cast<float4*>(out);
    #pragma unroll
    for (unsigned int k = 0; k < 4u; ++k) {
        unsigned int t = base + k * TPB;
        if (t >= total4) break;
        unsigned int off = t << 2;
        unsigned int m = off - N;
        unsigned int i = m >> shift;
        unsigned int j = m & mask;
        float4 r = make_float4(0.f, 0.f, 0.f, 0.f);
        if ((off < N) | (i < 2u) | (j == 0u)) {
            if (off < N) {
                if (off == 0u) { float hp = __ldg(&var[1]); r.x = hp; r.y = -hp; }
            } else {
                float mu0   = __ldg(&mu[0]);
                float mu1   = __ldg(&mu[1]);
                float var01 = __ldg(&var[1]);
                float c = var01 - 2.f * mu0 * mu1;
                if (i < 2u) {
                    float s = (i == 0u) ? 1.f : -1.f;
                    float* rr = &r.x;
                    #pragma unroll
                    for (int q = 0; q < 4; ++q) {
                        unsigned int jj = j + (unsigned int)q;
                        float vj = 0.f;
                        if (jj >= 2u)
                            vj = fmaf(__ldg(&mu[jj]), c,
                                  fmaf(mu1, __ldg(&var[jj]),
                                       mu0 * __ldg(&var[N + jj])));
                        rr[q] = s * vj;
                    }
                    if (j == 0u) corner2x2(mu, var, N, i, &r.x, &r.y);
                } else {
                    float vi = fmaf(__ldg(&mu[i]), c,
                                fmaf(mu1, __ldg(&var[i]),
                                     mu0 * __ldg(&var[N + i])));
                    r.x = vi; r.y = -vi;
                }
            }
        }
        __stcs(&out4[t], r);
    }
}

extern "C" void kernel_launch(void* const* d_in, const int* in_sizes, int n_in,
                              void* d_out, int out_size) {
    const float* mu  = (const float*)d_in[0];
    const float* var = (const float*)d_in[1];
    float* out = (float*)d_out;

    unsigned int N = (unsigned int)in_sizes[0];   // 8192

    long long expect = (long long)N + (long long)N * N;
    if (N == TPB * VPT * 4u && (long long)out_size == expect) {
        // One block per output row: block 0 = muTE, blocks 1..N = rows of M.
        eatrxn_row_kernel<<<N + 1u, TPB>>>(mu, var, out, N);
    } else {
        unsigned int shift = 0;
        while ((1u << shift) < N) ++shift;
        unsigned int mask = N - 1u;
        unsigned int total4 = (unsigned int)(out_size / 4);
        unsigned int per_block = TPB * 4u;
        unsigned int blocks = (total4 + per_block - 1) / per_block;
        eatrxn_generic_kernel<<<blocks, TPB>>>(mu, var, out, total4, N, shift, mask);
    }
}